// round 4
// baseline (speedup 1.0000x reference)
#include <cuda_runtime.h>
#include <stdint.h>
#include <math.h>

#define Tdim 288
#define BT 576
#define NROWS (BT*1024)
#define NELEM ((size_t)NROWS*64)

// ---------------- scratch (static device globals; no runtime alloc) ----------------
__device__ float g_Xp[NELEM];        // 151 MB
__device__ float g_T1[NELEM];        // 151 MB
__device__ float g_T2[NELEM];        // 151 MB
__device__ float g_L[1024*1024];     // tf32-rounded A, 4 MB
__device__ float g_dis[1024];
__device__ float g_v[2][1024];
__device__ float g_ss[24];
__device__ float g_lam;
__device__ float g_temp[Tdim*64];    // E_d+E_w+E_p
__device__ float g_ep[Tdim*64];      // E_p

// ---------------- helpers ----------------
__device__ __forceinline__ float blockReduceSum(float v){
    __shared__ float sh[32];
    int lane = threadIdx.x & 31, wid = threadIdx.x >> 5;
    #pragma unroll
    for(int o=16;o;o>>=1) v += __shfl_down_sync(0xffffffffu, v, o);
    if(lane==0) sh[wid]=v;
    __syncthreads();
    int nw = blockDim.x >> 5;
    v = (threadIdx.x < nw) ? sh[threadIdx.x] : 0.f;
    if(wid==0){
        #pragma unroll
        for(int o=16;o;o>>=1) v += __shfl_down_sync(0xffffffffu, v, o);
    }
    return v;  // valid in thread 0
}

__device__ __forceinline__ float tf32r(float f){
    uint32_t r; asm("cvt.rna.tf32.f32 %0, %1;" : "=r"(r) : "f"(f));
    return __uint_as_float(r);
}

// threefry2x32, 20 rounds (JAX threefry2x32_p), fully unrolled
__device__ __forceinline__ void threefry(uint32_t k0,uint32_t k1,uint32_t&x0,uint32_t&x1){
    uint32_t ks2 = k0^k1^0x1BD11BDAu;
    x0+=k0; x1+=k1;
    x0+=x1; x1=(x1<<13)|(x1>>19); x1^=x0;
    x0+=x1; x1=(x1<<15)|(x1>>17); x1^=x0;
    x0+=x1; x1=(x1<<26)|(x1>> 6); x1^=x0;
    x0+=x1; x1=(x1<< 6)|(x1>>26); x1^=x0;
    x0+=k1; x1+=ks2+1u;
    x0+=x1; x1=(x1<<17)|(x1>>15); x1^=x0;
    x0+=x1; x1=(x1<<29)|(x1>> 3); x1^=x0;
    x0+=x1; x1=(x1<<16)|(x1>>16); x1^=x0;
    x0+=x1; x1=(x1<<24)|(x1>> 8); x1^=x0;
    x0+=ks2; x1+=k0+2u;
    x0+=x1; x1=(x1<<13)|(x1>>19); x1^=x0;
    x0+=x1; x1=(x1<<15)|(x1>>17); x1^=x0;
    x0+=x1; x1=(x1<<26)|(x1>> 6); x1^=x0;
    x0+=x1; x1=(x1<< 6)|(x1>>26); x1^=x0;
    x0+=k0; x1+=k1+3u;
    x0+=x1; x1=(x1<<17)|(x1>>15); x1^=x0;
    x0+=x1; x1=(x1<<29)|(x1>> 3); x1^=x0;
    x0+=x1; x1=(x1<<16)|(x1>>16); x1^=x0;
    x0+=x1; x1=(x1<<24)|(x1>> 8); x1^=x0;
    x0+=k1; x1+=ks2+4u;
    x0+=x1; x1=(x1<<13)|(x1>>19); x1^=x0;
    x0+=x1; x1=(x1<<15)|(x1>>17); x1^=x0;
    x0+=x1; x1=(x1<<26)|(x1>> 6); x1^=x0;
    x0+=x1; x1=(x1<< 6)|(x1>>26); x1^=x0;
    x0+=ks2; x1+=k0+5u;
}

// XLA f32 ErfInv (Giles)
__device__ float erfinv_f(float x){
    float w = -log1pf(-x*x);
    float p;
    if (w < 5.0f){
        w -= 2.5f;
        p = 2.81022636e-08f;
        p = fmaf(p,w, 3.43273939e-07f);
        p = fmaf(p,w,-3.5233877e-06f);
        p = fmaf(p,w,-4.39150654e-06f);
        p = fmaf(p,w, 0.00021858087f);
        p = fmaf(p,w,-0.00125372503f);
        p = fmaf(p,w,-0.00417768164f);
        p = fmaf(p,w, 0.246640727f);
        p = fmaf(p,w, 1.50140941f);
    } else {
        w = sqrtf(w) - 3.0f;
        p = -0.000200214257f;
        p = fmaf(p,w, 0.000100950558f);
        p = fmaf(p,w, 0.00134934322f);
        p = fmaf(p,w,-0.00367342844f);
        p = fmaf(p,w, 0.00573950773f);
        p = fmaf(p,w,-0.0076224613f);
        p = fmaf(p,w, 0.00943887047f);
        p = fmaf(p,w, 1.00167406f);
        p = fmaf(p,w, 2.83297682f);
    }
    return p*x;
}

__device__ __forceinline__ float bits_to_normal(uint32_t bits){
    float u = __uint_as_float((bits>>9) | 0x3f800000u) - 1.0f; // [0,1)
    const float lo = -0.99999994f;                             // nextafter(-1,0)
    float val = u*2.0f + lo;                                   // (hi-lo) rounds to 2.0f
    val = fmaxf(val, lo);
    return 1.41421354f * erfinv_f(val);                        // sqrt(2) in f32
}

// ---------------- small kernels ----------------
__global__ void k_zero(){
    if(threadIdx.x < 24) g_ss[threadIdx.x] = 0.f;
    if(threadIdx.x == 0) g_lam = 0.f;
}

__global__ void k_dis(const float* __restrict__ A){
    int i = blockIdx.x;
    float s = 0.f;
    const float* row = A + (size_t)i*1024;
    for(int j=threadIdx.x;j<1024;j+=256) s += row[j];
    s = blockReduceSum(s);
    if(threadIdx.x==0) g_dis[i] = rsqrtf(s + 1e-12f);
}

// JAX partitionable threefry: per-element counter i -> threefry(key,(0,i)), 32-bit out = x0^x1
__global__ void k_init_v(){
    int i = threadIdx.x;                 // 0..1023, one block
    uint32_t x0 = 0u, x1 = (uint32_t)i;
    threefry(0u, 42u, x0, x1);
    uint32_t bits = x0 ^ x1;
    float a = bits_to_normal(bits);
    g_v[0][i] = a;
    float ss = blockReduceSum(a*a);
    if(i==0) g_ss[0] = ss;
}

// it in 1..20: v[it] = L @ normalize(v[it-1]); it==21: lam = v20n . (L v20n)
__global__ void k_matvec(const float* __restrict__ A, int it){
    int i = blockIdx.x;
    const float* vin = g_v[(it-1)&1];
    float ss_in = g_ss[it-1];
    float scale = 1.0f/(sqrtf(ss_in) + 1e-12f);
    const float* Arow = A + (size_t)i*1024;
    float s = 0.f;
    for(int j=threadIdx.x;j<1024;j+=256)
        s += Arow[j]*g_dis[j]*vin[j];
    s = blockReduceSum(s);
    if(threadIdx.x==0){
        float w = scale*(vin[i] - g_dis[i]*s);   // (L v_norm)_i
        if(it<=20){
            g_v[it&1][i] = w;
            atomicAdd(&g_ss[it], w*w);
        } else {
            atomicAdd(&g_lam, (vin[i]*scale)*w); // v_norm_i * (L v_norm)_i
        }
    }
}

// pre-round A to tf32 (reused 1152 times by the two cheb GEMMs)
__global__ void k_roundA(const float* __restrict__ A){
    for(size_t e = (size_t)blockIdx.x*blockDim.x + threadIdx.x;
        e < (size_t)1024*1024; e += (size_t)gridDim.x*blockDim.x)
        g_L[e] = tf32r(A[e]);
}

__global__ void k_temp(const float* __restrict__ eday, const float* __restrict__ eweek,
                       const int* __restrict__ mi, const int* __restrict__ wi){
    int t = blockIdx.x, d = threadIdx.x;   // 288 x 64
    int md = ((mi[t] % 288) + 288) % 288;
    int wd = ((wi[t] % 7) + 7) % 7;
    const float factor = (float)(-9.210340371976184/64.0);   // -ln(10000)/64
    float divv = expf((float)(d & ~1) * factor);
    float ang = (float)t * divv;
    float pe = (d & 1) ? cosf(ang) : sinf(ang);
    g_ep[t*64+d]   = pe;
    g_temp[t*64+d] = eday[md*64+d] + eweek[wd*64+d] + pe;
}

// Xp = X@W_in + b; X_te = LN(Xp + temp[t]). One warp per row.
__global__ void k_xp(const float* __restrict__ X, const float* __restrict__ Win,
                     const float* __restrict__ bin, const float* __restrict__ gam,
                     const float* __restrict__ bet, float* __restrict__ out_te){
    __shared__ float Ws[192], bs[64], gs[64], bes[64];
    int tid = threadIdx.x;
    if(tid < 192) Ws[tid] = Win[tid];
    else { int d = tid - 192; bs[d]=bin[d]; gs[d]=gam[d]; bes[d]=bet[d]; }
    __syncthreads();
    int r = blockIdx.x*8 + (tid>>5);
    int lane = tid & 31;
    int t = (r >> 10) % Tdim;
    const float* xr = X + (size_t)r*3;
    float x0 = xr[0], x1 = xr[1], x2 = xr[2];
    int dA = lane, dB = lane + 32;
    float xpa = fmaf(x2, Ws[128+dA], fmaf(x1, Ws[64+dA], x0*Ws[dA])) + bs[dA];
    float xpb = fmaf(x2, Ws[128+dB], fmaf(x1, Ws[64+dB], x0*Ws[dB])) + bs[dB];
    size_t base = (size_t)r*64;
    g_Xp[base+dA] = xpa;
    g_Xp[base+dB] = xpb;
    float za = xpa + g_temp[t*64+dA];
    float zb = xpb + g_temp[t*64+dB];
    float s = za+zb, q = za*za + zb*zb;
    #pragma unroll
    for(int o=16;o;o>>=1){ s += __shfl_xor_sync(0xffffffffu,s,o); q += __shfl_xor_sync(0xffffffffu,q,o); }
    float m = s*(1.f/64.f);
    float var = q*(1.f/64.f) - m*m;
    float rs = rsqrtf(var + 1e-5f);
    out_te[base+dA] = (za-m)*rs*gs[dA] + bes[dA];
    out_te[base+dB] = (zb-m)*rs*gs[dB] + bes[dB];
}

// ---------------- TF32 tensor-core Chebyshev GEMM ----------------
// mode 0: acc = A@(dis*Xp);  T1 = c1*Xp - c2*dis*acc
// mode 1: acc = A@(dis*T1);  T2 = 2*c1*T1 - 2*c2*dis*acc - Xp
// BM=128, BN=64, BK=16; 8 warps in 4(M)x2(N), warp tile 32x32 (2 Mtiles x 4 Ntiles of m16n8k8)
#define CB_BM 128
__global__ void __launch_bounds__(256,2) k_cheb(int mode){
    __shared__ __align__(16) float As[2][CB_BM][20];   // [m][k], pad->stride 20
    __shared__ __align__(16) float Bs[2][16][72];      // [k][n], pad->stride 72
    __shared__ float dis_s[1024];

    const float* Bsrc = mode ? g_T1 : g_Xp;
    float*       Cdst = mode ? g_T2 : g_T1;
    int bt = blockIdx.y;
    int m0 = blockIdx.x*CB_BM;
    int tid = threadIdx.x;
    const float* Bb = g_Xp;  // silence unused warn pattern
    Bb = Bsrc + (size_t)bt*65536;

    for(int i=tid;i<1024;i+=256) dis_s[i]=g_dis[i];

    float lam = fminf(fmaxf(g_lam,1e-6f),2.0f);
    float c2 = 2.0f/lam, c1 = c2 - 1.0f;

    int warp = tid>>5, lane = tid&31;
    int wm = (warp&3)*32, wn = (warp>>2)*32;
    int grp = lane>>2, tig = lane&3;

    float acc[2][4][4];
    #pragma unroll
    for(int a=0;a<2;a++)
        #pragma unroll
        for(int b=0;b<4;b++)
            #pragma unroll
            for(int c=0;c<4;c++) acc[a][b][c]=0.f;

    // A-tile addressing: per thread 2 float4: f = tid + p*256; row=f>>2, kcol=(f&3)*4
    int a_r0 = tid>>2,        a_c = (tid&3)*4;
    int a_r1 = (tid+256)>>2;
    // B-tile: kk = tid>>4 (0..15), d = (tid&15)*4
    int b_k = tid>>4, b_d = (tid&15)*4;

    __syncthreads();   // dis_s ready

    float4 aR0, aR1, bR;
    // prologue: load tile k0=0
    aR0 = *(const float4*)&g_L[(size_t)(m0+a_r0)*1024 + a_c];
    aR1 = *(const float4*)&g_L[(size_t)(m0+a_r1)*1024 + a_c];
    {
        float4 x = *(const float4*)&Bb[(size_t)b_k*64 + b_d];
        float ds = dis_s[b_k];
        bR.x=tf32r(x.x*ds); bR.y=tf32r(x.y*ds); bR.z=tf32r(x.z*ds); bR.w=tf32r(x.w*ds);
    }
    *(float4*)&As[0][a_r0][a_c] = aR0;
    *(float4*)&As[0][a_r1][a_c] = aR1;
    *(float4*)&Bs[0][b_k][b_d]  = bR;
    __syncthreads();

    int buf = 0;
    for(int k0=0;k0<1024;k0+=16){
        int kn = k0+16;
        if(kn < 1024){
            aR0 = *(const float4*)&g_L[(size_t)(m0+a_r0)*1024 + kn + a_c];
            aR1 = *(const float4*)&g_L[(size_t)(m0+a_r1)*1024 + kn + a_c];
            float4 x = *(const float4*)&Bb[(size_t)(kn+b_k)*64 + b_d];
            float ds = dis_s[kn+b_k];
            bR.x=tf32r(x.x*ds); bR.y=tf32r(x.y*ds); bR.z=tf32r(x.z*ds); bR.w=tf32r(x.w*ds);
        }
        // compute on buf
        #pragma unroll
        for(int ks=0;ks<2;ks++){
            uint32_t af[2][4], bf[4][2];
            int kb = ks*8 + tig;
            #pragma unroll
            for(int mt=0;mt<2;mt++){
                int m = wm + mt*16 + grp;
                af[mt][0] = __float_as_uint(As[buf][m  ][kb  ]);
                af[mt][1] = __float_as_uint(As[buf][m+8][kb  ]);
                af[mt][2] = __float_as_uint(As[buf][m  ][kb+4]);
                af[mt][3] = __float_as_uint(As[buf][m+8][kb+4]);
            }
            #pragma unroll
            for(int nt=0;nt<4;nt++){
                int n = wn + nt*8 + grp;
                bf[nt][0] = __float_as_uint(Bs[buf][kb  ][n]);
                bf[nt][1] = __float_as_uint(Bs[buf][kb+4][n]);
            }
            #pragma unroll
            for(int mt=0;mt<2;mt++)
                #pragma unroll
                for(int nt=0;nt<4;nt++){
                    asm volatile(
                        "mma.sync.aligned.m16n8k8.row.col.f32.tf32.tf32.f32 "
                        "{%0,%1,%2,%3}, {%4,%5,%6,%7}, {%8,%9}, {%0,%1,%2,%3};\n"
                        : "+f"(acc[mt][nt][0]), "+f"(acc[mt][nt][1]),
                          "+f"(acc[mt][nt][2]), "+f"(acc[mt][nt][3])
                        : "r"(af[mt][0]), "r"(af[mt][1]), "r"(af[mt][2]), "r"(af[mt][3]),
                          "r"(bf[nt][0]), "r"(bf[nt][1]));
                }
        }
        if(kn < 1024){
            int nb = buf^1;
            *(float4*)&As[nb][a_r0][a_c] = aR0;
            *(float4*)&As[nb][a_r1][a_c] = aR1;
            *(float4*)&Bs[nb][b_k][b_d]  = bR;
            __syncthreads();
            buf = nb;
        }
    }

    // epilogue
    size_t base = (size_t)bt*65536;
    #pragma unroll
    for(int mt=0;mt<2;mt++){
        #pragma unroll
        for(int h=0;h<2;h++){
            int rloc = wm + mt*16 + grp + 8*h;       // node index within 0..1023 (block-local + m0)
            int r = m0 + rloc;
            float dsr = dis_s[r];
            #pragma unroll
            for(int nt=0;nt<4;nt++){
                int col = wn + nt*8 + 2*tig;
                size_t idx = base + (size_t)r*64 + col;
                float a0 = acc[mt][nt][2*h], a1 = acc[mt][nt][2*h+1];
                float2 xp = *(const float2*)&g_Xp[idx];
                float2 o;
                if(mode==0){
                    o.x = c1*xp.x - c2*dsr*a0;
                    o.y = c1*xp.y - c2*dsr*a1;
                } else {
                    float2 t1v = *(const float2*)&g_T1[idx];
                    o.x = 2.f*(c1*t1v.x - c2*dsr*a0) - xp.x;
                    o.y = 2.f*(c1*t1v.y - c2*dsr*a1) - xp.y;
                }
                *(float2*)&Cdst[idx] = o;
            }
        }
    }
}

// out_s = [Xp|T1|T2] @ [th0;th1;th2]  (K=192), then X_sp = LN(Xp + out_s + cbias + ep)
__global__ void k_combine(const float* __restrict__ theta, const float* __restrict__ cbias,
                          const float* __restrict__ gam, const float* __restrict__ bet,
                          float* __restrict__ out_sp){
    extern __shared__ float sm[];
    float* Th = sm;              // 192*64
    float* As = sm + 192*64;     // 16*132
    int tid = threadIdx.x;
    for(int e=tid; e<192*64; e+=256) Th[e] = theta[e];
    int row0 = blockIdx.x * 128;
    int tx = tid & 15, ty = tid >> 4;
    float acc[8][4];
    #pragma unroll
    for(int i=0;i<8;i++)
        #pragma unroll
        for(int j=0;j<4;j++) acc[i][j]=0.f;
    __syncthreads();

    for(int k0=0;k0<192;k0+=16){
        const float* Src = (k0<64) ? g_Xp : ((k0<128) ? g_T1 : g_T2);
        int col0 = k0 & 63;
        #pragma unroll
        for(int p=0;p<8;p++){
            int m = p*16 + (tid>>4);
            int k = tid & 15;
            As[k*132+m] = Src[(size_t)(row0+m)*64 + col0 + k];
        }
        __syncthreads();
        #pragma unroll
        for(int kk=0;kk<16;kk++){
            float a[8], b[4];
            #pragma unroll
            for(int i=0;i<8;i++) a[i] = As[kk*132 + ty*8 + i];
            #pragma unroll
            for(int j=0;j<4;j++) b[j] = Th[(k0+kk)*64 + tx*4 + j];
            #pragma unroll
            for(int i=0;i<8;i++)
                #pragma unroll
                for(int j=0;j<4;j++) acc[i][j] = fmaf(a[i], b[j], acc[i][j]);
        }
        __syncthreads();
    }

    int t = (row0 >> 10) % Tdim;   // 128 rows share same bt
    #pragma unroll
    for(int i=0;i<8;i++){
        int r = row0 + ty*8 + i;
        float z[4];
        float s = 0.f, q = 0.f;
        #pragma unroll
        for(int j=0;j<4;j++){
            int c = tx*4 + j;
            z[j] = acc[i][j] + g_Xp[(size_t)r*64 + c] + cbias[c] + g_ep[t*64 + c];
            s += z[j]; q += z[j]*z[j];
        }
        #pragma unroll
        for(int o=8;o;o>>=1){ s += __shfl_xor_sync(0xffffffffu,s,o); q += __shfl_xor_sync(0xffffffffu,q,o); }
        float m = s*(1.f/64.f);
        float var = q*(1.f/64.f) - m*m;
        float rs = rsqrtf(var + 1e-5f);
        #pragma unroll
        for(int j=0;j<4;j++){
            int c = tx*4 + j;
            out_sp[(size_t)r*64 + c] = (z[j]-m)*rs*gam[c] + bet[c];
        }
    }
}

// ---------------- launch ----------------
extern "C" void kernel_launch(void* const* d_in, const int* in_sizes, int n_in,
                              void* d_out, int out_size){
    const float* X     = (const float*)d_in[0];
    const float* A     = (const float*)d_in[1];
    const float* Win   = (const float*)d_in[2];
    const float* bin   = (const float*)d_in[3];
    const float* theta = (const float*)d_in[4];
    const float* cbias = (const float*)d_in[5];
    const float* eday  = (const float*)d_in[6];
    const float* eweek = (const float*)d_in[7];
    const float* gam   = (const float*)d_in[8];
    const float* bet   = (const float*)d_in[9];
    const int*   mi    = (const int*)d_in[10];
    const int*   wi    = (const int*)d_in[11];
    float* out = (float*)d_out;

    const int SMEM_COMBINE = (192*64 + 16*132)*4;   // 57600 B
    cudaFuncSetAttribute(k_combine, cudaFuncAttributeMaxDynamicSharedMemorySize, SMEM_COMBINE);

    k_zero<<<1,32>>>();
    k_dis<<<1024,256>>>(A);
    k_init_v<<<1,1024>>>();
    k_roundA<<<1024,256>>>(A);
    k_temp<<<Tdim,64>>>(eday, eweek, mi, wi);
    k_xp<<<NROWS/8,256>>>(X, Win, bin, gam, bet, out);           // writes Xp + X_te
    for(int it=1; it<=21; ++it)
        k_matvec<<<1024,256>>>(A, it);
    k_cheb<<<dim3(8,BT),256>>>(0);                                // T1 (tensor core)
    k_cheb<<<dim3(8,BT),256>>>(1);                                // T2 (tensor core)
    k_combine<<<NROWS/128,256,SMEM_COMBINE>>>(theta, cbias, gam, bet, out + NELEM);  // X_sp
}

// round 5
// speedup vs baseline: 2.5604x; 2.5604x over previous
#include <cuda_runtime.h>
#include <cuda_fp16.h>
#include <stdint.h>
#include <math.h>

#define Tdim 288
#define BT 576
#define NROWS (BT*1024)
#define NELEM ((size_t)NROWS*64)

__device__ float  g_Xp[NELEM];
__device__ float  g_T1[NELEM];          // S1
__device__ float  g_T2[NELEM];          // S2
__device__ float  g_L[1024*1024];       // tf32 An
__device__ __half g_Lh[2048*1024];      // fp16 [An ; An^2]
__device__ float  g_Th[3*64*64];        // folded thetas (tf32)
__device__ float  g_dis[1024];
__device__ float  g_v[2][1024];
__device__ float  g_ss[24];
__device__ float  g_lam;
__device__ float  g_temp[Tdim*64];
__device__ float  g_ep[Tdim*64];

__device__ __forceinline__ float blockReduceSum(float v){
    __shared__ float sh[32];
    int lane = threadIdx.x & 31, wid = threadIdx.x >> 5;
    #pragma unroll
    for(int o=16;o;o>>=1) v += __shfl_down_sync(0xffffffffu, v, o);
    if(lane==0) sh[wid]=v;
    __syncthreads();
    int nw = blockDim.x >> 5;
    v = (threadIdx.x < nw) ? sh[threadIdx.x] : 0.f;
    if(wid==0){
        #pragma unroll
        for(int o=16;o;o>>=1) v += __shfl_down_sync(0xffffffffu, v, o);
    }
    return v;
}

__device__ __forceinline__ float tf32r(float f){
    uint32_t r; asm("cvt.rna.tf32.f32 %0, %1;" : "=r"(r) : "f"(f));
    return __uint_as_float(r);
}

__device__ __forceinline__ void threefry(uint32_t k0,uint32_t k1,uint32_t&x0,uint32_t&x1){
    uint32_t ks2 = k0^k1^0x1BD11BDAu;
    x0+=k0; x1+=k1;
    x0+=x1; x1=(x1<<13)|(x1>>19); x1^=x0;
    x0+=x1; x1=(x1<<15)|(x1>>17); x1^=x0;
    x0+=x1; x1=(x1<<26)|(x1>> 6); x1^=x0;
    x0+=x1; x1=(x1<< 6)|(x1>>26); x1^=x0;
    x0+=k1; x1+=ks2+1u;
    x0+=x1; x1=(x1<<17)|(x1>>15); x1^=x0;
    x0+=x1; x1=(x1<<29)|(x1>> 3); x1^=x0;
    x0+=x1; x1=(x1<<16)|(x1>>16); x1^=x0;
    x0+=x1; x1=(x1<<24)|(x1>> 8); x1^=x0;
    x0+=ks2; x1+=k0+2u;
    x0+=x1; x1=(x1<<13)|(x1>>19); x1^=x0;
    x0+=x1; x1=(x1<<15)|(x1>>17); x1^=x0;
    x0+=x1; x1=(x1<<26)|(x1>> 6); x1^=x0;
    x0+=x1; x1=(x1<< 6)|(x1>>26); x1^=x0;
    x0+=k0; x1+=k1+3u;
    x0+=x1; x1=(x1<<17)|(x1>>15); x1^=x0;
    x0+=x1; x1=(x1<<29)|(x1>> 3); x1^=x0;
    x0+=x1; x1=(x1<<16)|(x1>>16); x1^=x0;
    x0+=x1; x1=(x1<<24)|(x1>> 8); x1^=x0;
    x0+=k1; x1+=ks2+4u;
    x0+=x1; x1=(x1<<13)|(x1>>19); x1^=x0;
    x0+=x1; x1=(x1<<15)|(x1>>17); x1^=x0;
    x0+=x1; x1=(x1<<26)|(x1>> 6); x1^=x0;
    x0+=x1; x1=(x1<< 6)|(x1>>26); x1^=x0;
    x0+=ks2; x1+=k0+5u;
}

__device__ float erfinv_f(float x){
    float w = -log1pf(-x*x);
    float p;
    if (w < 5.0f){
        w -= 2.5f;
        p = 2.81022636e-08f;
        p = fmaf(p,w, 3.43273939e-07f);
        p = fmaf(p,w,-3.5233877e-06f);
        p = fmaf(p,w,-4.39150654e-06f);
        p = fmaf(p,w, 0.00021858087f);
        p = fmaf(p,w,-0.00125372503f);
        p = fmaf(p,w,-0.00417768164f);
        p = fmaf(p,w, 0.246640727f);
        p = fmaf(p,w, 1.50140941f);
    } else {
        w = sqrtf(w) - 3.0f;
        p = -0.000200214257f;
        p = fmaf(p,w, 0.000100950558f);
        p = fmaf(p,w, 0.00134934322f);
        p = fmaf(p,w,-0.00367342844f);
        p = fmaf(p,w, 0.00573950773f);
        p = fmaf(p,w,-0.0076224613f);
        p = fmaf(p,w, 0.00943887047f);
        p = fmaf(p,w, 1.00167406f);
        p = fmaf(p,w, 2.83297682f);
    }
    return p*x;
}

__device__ __forceinline__ float bits_to_normal(uint32_t bits){
    float u = __uint_as_float((bits>>9) | 0x3f800000u) - 1.0f;
    const float lo = -0.99999994f;
    float val = u*2.0f + lo;
    val = fmaxf(val, lo);
    return 1.41421354f * erfinv_f(val);
}

// ---------- small kernels ----------
__global__ void k_dis_init(const float* __restrict__ A){
    int b = blockIdx.x;
    if(b < 1024){
        float s = 0.f;
        const float* row = A + (size_t)b*1024;
        for(int j=threadIdx.x;j<1024;j+=256) s += row[j];
        s = blockReduceSum(s);
        if(threadIdx.x==0) g_dis[b] = rsqrtf(s + 1e-12f);
    } else {
        if(threadIdx.x < 24) g_ss[threadIdx.x] = 0.f;
        if(threadIdx.x == 0) g_lam = 0.f;
        float loc = 0.f;
        #pragma unroll
        for(int c=0;c<4;c++){
            int i = threadIdx.x*4 + c;
            uint32_t x0 = 0u, x1 = (uint32_t)i;
            threefry(0u, 42u, x0, x1);
            float a = bits_to_normal(x0 ^ x1);
            g_v[0][i] = a;
            loc += a*a;
        }
        float ss = blockReduceSum(loc);
        if(threadIdx.x==0) g_ss[0] = ss;
    }
}

__global__ void k_prepA(const float* __restrict__ A){
    int i = blockIdx.x;
    float di = g_dis[i];
    for(int j=threadIdx.x;j<1024;j+=256){
        float v = di * A[(size_t)i*1024+j] * g_dis[j];
        g_L[(size_t)i*1024+j]  = tf32r(v);
        g_Lh[(size_t)i*1024+j] = __float2half(v);
    }
}

__global__ void k_matvec(const float* __restrict__ A, int it){
    int row = blockIdx.x*8 + (threadIdx.x>>5);
    int lane = threadIdx.x & 31;
    const float* vin = g_v[(it-1)&1];
    float scale = 1.0f/(sqrtf(g_ss[it-1]) + 1e-12f);
    const float* Ar = A + (size_t)row*1024;
    float s = 0.f;
    #pragma unroll
    for(int j=0;j<32;j++) s += Ar[lane + 32*j]*g_dis[lane+32*j]*vin[lane+32*j];
    #pragma unroll
    for(int o=16;o;o>>=1) s += __shfl_down_sync(0xffffffffu, s, o);
    if(lane==0){
        float w = scale*(vin[row] - g_dis[row]*s);
        if(it<=20){ g_v[it&1][row] = w; atomicAdd(&g_ss[it], w*w); }
        else atomicAdd(&g_lam, (vin[row]*scale)*w);
    }
}

// An2 = An@An (tf32), store fp16 into g_Lh rows 1024..2047
__global__ void __launch_bounds__(256) k_an2(){
    __shared__ float As[128][20];
    __shared__ float Bs[16][72];
    int m0 = blockIdx.x*128, n0 = blockIdx.y*64;
    int tid = threadIdx.x, warp = tid>>5, lane = tid&31, grp = lane>>2, tig = lane&3;
    int wm = (warp&3)*32, wn = (warp>>2)*32;
    float acc[2][4][4];
    #pragma unroll
    for(int a=0;a<2;a++)
        #pragma unroll
        for(int b=0;b<4;b++)
            #pragma unroll
            for(int c=0;c<4;c++) acc[a][b][c]=0.f;
    for(int k0=0;k0<1024;k0+=16){
        #pragma unroll
        for(int c=0;c<2;c++){
            int q = tid + 256*c; int row = q>>2, kc = (q&3)*4;
            *(float4*)&As[row][kc] = *(const float4*)&g_L[(size_t)(m0+row)*1024 + k0 + kc];
        }
        { int kk = tid>>4, d = (tid&15)*4;
          *(float4*)&Bs[kk][d] = *(const float4*)&g_L[(size_t)(k0+kk)*1024 + n0 + d]; }
        __syncthreads();
        #pragma unroll
        for(int ks=0;ks<2;ks++){
            int kb = ks*8 + tig;
            uint32_t a[2][4], bf[4][2];
            #pragma unroll
            for(int mt=0;mt<2;mt++){
                int m = wm + mt*16 + grp;
                a[mt][0]=__float_as_uint(As[m  ][kb  ]);
                a[mt][1]=__float_as_uint(As[m+8][kb  ]);
                a[mt][2]=__float_as_uint(As[m  ][kb+4]);
                a[mt][3]=__float_as_uint(As[m+8][kb+4]);
            }
            #pragma unroll
            for(int nt=0;nt<4;nt++){
                int n = wn + nt*8 + grp;
                bf[nt][0]=__float_as_uint(Bs[kb  ][n]);
                bf[nt][1]=__float_as_uint(Bs[kb+4][n]);
            }
            #pragma unroll
            for(int mt=0;mt<2;mt++)
                #pragma unroll
                for(int nt=0;nt<4;nt++)
                    asm volatile("mma.sync.aligned.m16n8k8.row.col.f32.tf32.tf32.f32 "
                        "{%0,%1,%2,%3}, {%4,%5,%6,%7}, {%8,%9}, {%0,%1,%2,%3};\n"
                        : "+f"(acc[mt][nt][0]),"+f"(acc[mt][nt][1]),"+f"(acc[mt][nt][2]),"+f"(acc[mt][nt][3])
                        : "r"(a[mt][0]),"r"(a[mt][1]),"r"(a[mt][2]),"r"(a[mt][3]),
                          "r"(bf[nt][0]),"r"(bf[nt][1]));
        }
        __syncthreads();
    }
    #pragma unroll
    for(int mt=0;mt<2;mt++)
        #pragma unroll
        for(int h=0;h<2;h++){
            int r = m0 + wm + mt*16 + grp + 8*h;
            #pragma unroll
            for(int nt=0;nt<4;nt++){
                int c = n0 + wn + nt*8 + 2*tig;
                __half2 hv = __floats2half2_rn(acc[mt][nt][2*h], acc[mt][nt][2*h+1]);
                *(uint32_t*)&g_Lh[(size_t)(1024+r)*1024 + c] = *(uint32_t*)&hv;
            }
        }
}

__global__ void k_temp(const float* __restrict__ eday, const float* __restrict__ eweek,
                       const int* __restrict__ mi, const int* __restrict__ wi){
    int t = blockIdx.x, d = threadIdx.x;
    int md = ((mi[t] % 288) + 288) % 288;
    int wd = ((wi[t] % 7) + 7) % 7;
    const float factor = (float)(-9.210340371976184/64.0);
    float divv = expf((float)(d & ~1) * factor);
    float ang = (float)t * divv;
    float pe = (d & 1) ? cosf(ang) : sinf(ang);
    g_ep[t*64+d]   = pe;
    g_temp[t*64+d] = eday[md*64+d] + eweek[wd*64+d] + pe;
}

// folded thetas (needs g_lam): K order [Xp | S1 | S2]
__global__ void k_theta(const float* __restrict__ theta){
    float lam = fminf(fmaxf(g_lam,1e-6f),2.0f);
    float c2 = 2.0f/lam, c1 = c2 - 1.0f;
    int idx = threadIdx.x + blockIdx.x*256;
    if(idx < 4096){
        float t0 = theta[idx], t1 = theta[4096+idx], t2 = theta[8192+idx];
        g_Th[idx]      = tf32r(t0 + c1*t1 + (2.0f*c1*c1 - 1.0f)*t2);
        g_Th[4096+idx] = tf32r(-c2*t1 - 4.0f*c1*c2*t2);
        g_Th[8192+idx] = tf32r(2.0f*c2*c2*t2);
    }
}

__global__ void k_xp(const float* __restrict__ X, const float* __restrict__ Win,
                     const float* __restrict__ bin, const float* __restrict__ gam,
                     const float* __restrict__ bet, float* __restrict__ out_te){
    __shared__ float Ws[192], bs[64], gs[64], bes[64];
    int tid = threadIdx.x;
    if(tid < 192) Ws[tid] = Win[tid];
    else { int d = tid - 192; bs[d]=bin[d]; gs[d]=gam[d]; bes[d]=bet[d]; }
    __syncthreads();
    int r = blockIdx.x*8 + (tid>>5);
    int lane = tid & 31;
    int t = (r >> 10) % Tdim;
    const float* xr = X + (size_t)r*3;
    float x0 = xr[0], x1 = xr[1], x2 = xr[2];
    int dA = lane, dB = lane + 32;
    float xpa = fmaf(x2, Ws[128+dA], fmaf(x1, Ws[64+dA], x0*Ws[dA])) + bs[dA];
    float xpb = fmaf(x2, Ws[128+dB], fmaf(x1, Ws[64+dB], x0*Ws[dB])) + bs[dB];
    size_t base = (size_t)r*64;
    g_Xp[base+dA] = xpa;
    g_Xp[base+dB] = xpb;
    float za = xpa + g_temp[t*64+dA];
    float zb = xpb + g_temp[t*64+dB];
    float s = za+zb, q = za*za + zb*zb;
    #pragma unroll
    for(int o=16;o;o>>=1){ s += __shfl_xor_sync(0xffffffffu,s,o); q += __shfl_xor_sync(0xffffffffu,q,o); }
    float m = s*(1.f/64.f);
    float var = q*(1.f/64.f) - m*m;
    float rs = rsqrtf(var + 1e-5f);
    out_te[base+dA] = (za-m)*rs*gs[dA] + bes[dA];
    out_te[base+dB] = (zb-m)*rs*gs[dB] + bes[dB];
}

// ---------- fused S1,S2 = [An;An2] @ Xp  (fp16 HMMA, cp.async x4) ----------
// BM=256 (stacked), BN=128 (bt pair), BK=32. 512 threads = 16 warps (4m x 4n).
#define FS_A 0          // 4 stages * 256*80B = 81920
#define FS_B 81920      // 2 stages * 32*272B = 17408  (total 99328)
__global__ void __launch_bounds__(512,1) k_fused(){
    extern __shared__ char sm[];
    uint32_t sb = (uint32_t)__cvta_generic_to_shared(sm);
    int tid = threadIdx.x, warp = tid>>5, lane = tid&31;
    int grp = lane>>2, tig = lane&3;
    int gm0 = blockIdx.x*256;
    const float* XpB = g_Xp + (size_t)(2*blockIdx.y)*65536;
    int wm = (warp&3)*64, wn = (warp>>2)*32;
    float acc[4][4][4];
    #pragma unroll
    for(int a=0;a<4;a++)
        #pragma unroll
        for(int b=0;b<4;b++)
            #pragma unroll
            for(int c=0;c<4;c++) acc[a][b][c]=0.f;

    int n4 = lane*4;
    size_t boff = (size_t)(n4>>6)*65536 + (n4&63);
    int kw = 2*warp;                         // warp 0..15 -> k rows 2w,2w+1
    int a_row = tid>>2, a_part = tid&3;
    float4 rb0, rb1;

#define ISSUE_A(I) do{ int _i=(I); if(_i<32){ \
    uint32_t d0 = sb + FS_A + (_i&3)*20480 + a_row*80 + a_part*16; \
    const __half* s0 = g_Lh + (size_t)(gm0+a_row)*1024 + _i*32 + a_part*8; \
    asm volatile("cp.async.cg.shared.global [%0], [%1], 16;\n"::"r"(d0),"l"(s0)); \
    const __half* s1 = g_Lh + (size_t)(gm0+128+a_row)*1024 + _i*32 + a_part*8; \
    asm volatile("cp.async.cg.shared.global [%0], [%1], 16;\n"::"r"(d0+128*80),"l"(s1)); } \
    asm volatile("cp.async.commit_group;\n"); }while(0)
#define LDG_B(I) do{ int _i=(I); if(_i<32){ \
    rb0 = *(const float4*)(XpB + boff + (size_t)(_i*32 + kw)*64); \
    rb1 = *(const float4*)(XpB + boff + (size_t)(_i*32 + kw+1)*64); } }while(0)
#define STS_B(I) do{ int _i=(I); if(_i<32){ \
    char* p0 = sm + FS_B + (_i&1)*8704 + kw*272 + n4*2; \
    *(__half2*)(p0)     = __floats2half2_rn(rb0.x, rb0.y); \
    *(__half2*)(p0+4)   = __floats2half2_rn(rb0.z, rb0.w); \
    *(__half2*)(p0+272) = __floats2half2_rn(rb1.x, rb1.y); \
    *(__half2*)(p0+276) = __floats2half2_rn(rb1.z, rb1.w); } }while(0)

    ISSUE_A(0); ISSUE_A(1); ISSUE_A(2);
    LDG_B(0); STS_B(0); LDG_B(1);

    for(int i=0;i<32;i++){
        asm volatile("cp.async.wait_group 2;\n");
        __syncthreads();
        ISSUE_A(i+3);
        STS_B(i+1);
        LDG_B(i+2);
        uint32_t Au = sb + FS_A + (i&3)*20480;
        uint32_t Bu = sb + FS_B + (i&1)*8704;
        #pragma unroll
        for(int ks=0;ks<2;ks++){
            uint32_t bf[4][2];
            #pragma unroll
            for(int nt=0;nt<4;nt++){
                uint32_t ad = Bu + (ks*16 + (lane&15))*272 + (wn + nt*8)*2;
                asm volatile("ldmatrix.sync.aligned.m8n8.x2.trans.shared.b16 {%0,%1}, [%2];\n"
                             : "=r"(bf[nt][0]), "=r"(bf[nt][1]) : "r"(ad));
            }
            #pragma unroll
            for(int mt=0;mt<4;mt++){
                uint32_t a0,a1,a2,a3;
                uint32_t ad = Au + (wm + mt*16 + ((lane>>3)&1)*8 + (lane&7))*80
                              + (ks*16 + (lane>>4)*8)*2;
                asm volatile("ldmatrix.sync.aligned.m8n8.x4.shared.b16 {%0,%1,%2,%3}, [%4];\n"
                             : "=r"(a0),"=r"(a1),"=r"(a2),"=r"(a3) : "r"(ad));
                #pragma unroll
                for(int nt=0;nt<4;nt++)
                    asm volatile("mma.sync.aligned.m16n8k16.row.col.f32.f16.f16.f32 "
                        "{%0,%1,%2,%3}, {%4,%5,%6,%7}, {%8,%9}, {%0,%1,%2,%3};\n"
                        : "+f"(acc[mt][nt][0]),"+f"(acc[mt][nt][1]),"+f"(acc[mt][nt][2]),"+f"(acc[mt][nt][3])
                        : "r"(a0),"r"(a1),"r"(a2),"r"(a3),"r"(bf[nt][0]),"r"(bf[nt][1]));
            }
        }
    }
    float* Sd = (gm0 >= 1024) ? g_T2 : g_T1;
    #pragma unroll
    for(int mt=0;mt<4;mt++)
        #pragma unroll
        for(int h=0;h<2;h++){
            int node = (gm0 + wm + mt*16 + grp + 8*h) & 1023;
            #pragma unroll
            for(int nt=0;nt<4;nt++){
                int n = wn + nt*8 + 2*tig;
                size_t dst = (size_t)(2*blockIdx.y + (n>>6))*65536 + (size_t)node*64 + (n&63);
                *(float2*)&Sd[dst] = make_float2(acc[mt][nt][2*h], acc[mt][nt][2*h+1]);
            }
        }
#undef ISSUE_A
#undef LDG_B
#undef STS_B
}

// ---------- combine: out_s = Xp@Thx + S1@Th1 + S2@Th2, X_sp = LN(Xp+out_s+cbias+ep) ----------
#define CS_TH 0          // 192*68*4 = 52224 (Z aliases this after the loop)
#define CS_A  52224      // 4 stages * 128*80B = 40960
#define CS_ADD 93184
#define CS_G   93440
#define CS_BE  93696     // total 93952
__global__ void __launch_bounds__(256,2) k_combine(const float* __restrict__ cbias,
                    const float* __restrict__ gam, const float* __restrict__ bet,
                    float* __restrict__ out_sp){
    extern __shared__ char sm[];
    uint32_t sb = (uint32_t)__cvta_generic_to_shared(sm);
    float* Th = (float*)sm;
    float* sAdd = (float*)(sm + CS_ADD);
    float* sG = (float*)(sm + CS_G);
    float* sBe = (float*)(sm + CS_BE);
    int tid = threadIdx.x, warp = tid>>5, lane = tid&31, grp = lane>>2, tig = lane&3;
    int wm = (warp&3)*32, wn = (warp>>2)*32;
    int row0 = blockIdx.x*128;
    int t = (row0 >> 10) % Tdim;
    const float* arr0 = g_Xp + (size_t)row0*64;
    const float* arr1 = g_T1 + (size_t)row0*64;
    const float* arr2 = g_T2 + (size_t)row0*64;

#define ISSUE_C(I) do{ int _i=(I); if(_i<12){ \
    const float* S = (_i<4)? arr0 : ((_i<8)? arr1 : arr2); \
    _Pragma("unroll") \
    for(int c=0;c<2;c++){ int q = tid + 256*c; int row = q>>2, part = q&3; \
        uint32_t d = sb + CS_A + (_i&3)*10240 + row*80 + part*16; \
        const float* s = S + (size_t)row*64 + (_i&3)*16 + part*4; \
        asm volatile("cp.async.cg.shared.global [%0], [%1], 16;\n"::"r"(d),"l"(s)); } } \
    asm volatile("cp.async.commit_group;\n"); }while(0)

    ISSUE_C(0); ISSUE_C(1); ISSUE_C(2);
    #pragma unroll
    for(int c=0;c<12;c++){
        int q = tid + 256*c; int k = q>>4, n = (q&15)*4;
        *(float4*)&Th[k*68+n] = *(const float4*)&g_Th[k*64+n];
    }
    if(tid < 64){
        sAdd[tid] = cbias[tid] + g_ep[t*64+tid];
        sG[tid] = gam[tid]; sBe[tid] = bet[tid];
    }
    float acc[2][4][4];
    #pragma unroll
    for(int a=0;a<2;a++)
        #pragma unroll
        for(int b=0;b<4;b++)
            #pragma unroll
            for(int c=0;c<4;c++) acc[a][b][c]=0.f;

    for(int i=0;i<12;i++){
        asm volatile("cp.async.wait_group 2;\n");
        __syncthreads();
        ISSUE_C(i+3);
        float* As = (float*)(sm + CS_A + (i&3)*10240);
        #pragma unroll
        for(int ks=0;ks<2;ks++){
            int kb = ks*8 + tig;
            uint32_t a[2][4], bf[4][2];
            #pragma unroll
            for(int mt=0;mt<2;mt++){
                int m = wm + mt*16 + grp;
                a[mt][0]=__float_as_uint(As[m*20+kb]);
                a[mt][1]=__float_as_uint(As[(m+8)*20+kb]);
                a[mt][2]=__float_as_uint(As[m*20+kb+4]);
                a[mt][3]=__float_as_uint(As[(m+8)*20+kb+4]);
            }
            #pragma unroll
            for(int nt=0;nt<4;nt++){
                int n = wn + nt*8 + grp;
                bf[nt][0]=__float_as_uint(Th[(i*16+kb)*68+n]);
                bf[nt][1]=__float_as_uint(Th[(i*16+kb+4)*68+n]);
            }
            #pragma unroll
            for(int mt=0;mt<2;mt++)
                #pragma unroll
                for(int nt=0;nt<4;nt++)
                    asm volatile("mma.sync.aligned.m16n8k8.row.col.f32.tf32.tf32.f32 "
                        "{%0,%1,%2,%3}, {%4,%5,%6,%7}, {%8,%9}, {%0,%1,%2,%3};\n"
                        : "+f"(acc[mt][nt][0]),"+f"(acc[mt][nt][1]),"+f"(acc[mt][nt][2]),"+f"(acc[mt][nt][3])
                        : "r"(a[mt][0]),"r"(a[mt][1]),"r"(a[mt][2]),"r"(a[mt][3]),
                          "r"(bf[nt][0]),"r"(bf[nt][1]));
        }
    }
    __syncthreads();
    float* Z = (float*)sm;   // alias Th
    #pragma unroll
    for(int mt=0;mt<2;mt++)
        #pragma unroll
        for(int h=0;h<2;h++){
            int rloc = wm + mt*16 + grp + 8*h;
            #pragma unroll
            for(int nt=0;nt<4;nt++){
                int c = wn + nt*8 + 2*tig;
                float2 xp = *(const float2*)&g_Xp[(size_t)(row0+rloc)*64 + c];
                Z[rloc*68+c]   = acc[mt][nt][2*h]   + xp.x + sAdd[c];
                Z[rloc*68+c+1] = acc[mt][nt][2*h+1] + xp.y + sAdd[c+1];
            }
        }
    __syncthreads();
    #pragma unroll
    for(int it=0;it<8;it++){
        int r = (tid>>4) + 16*it;
        int cb = (tid&15)*4;
        float4 z = *(float4*)&Z[r*68 + cb];
        float s = z.x+z.y+z.z+z.w;
        float q = z.x*z.x+z.y*z.y+z.z*z.z+z.w*z.w;
        #pragma unroll
        for(int o=8;o;o>>=1){ s += __shfl_xor_sync(0xffffffffu,s,o); q += __shfl_xor_sync(0xffffffffu,q,o); }
        float m = s*(1.f/64.f);
        float rs = rsqrtf(q*(1.f/64.f) - m*m + 1e-5f);
        float4 o;
        o.x = (z.x-m)*rs*sG[cb]   + sBe[cb];
        o.y = (z.y-m)*rs*sG[cb+1] + sBe[cb+1];
        o.z = (z.z-m)*rs*sG[cb+2] + sBe[cb+2];
        o.w = (z.w-m)*rs*sG[cb+3] + sBe[cb+3];
        *(float4*)&out_sp[(size_t)(row0+r)*64 + cb] = o;
    }
#undef ISSUE_C
}

// ---------- launch ----------
extern "C" void kernel_launch(void* const* d_in, const int* in_sizes, int n_in,
                              void* d_out, int out_size){
    const float* X     = (const float*)d_in[0];
    const float* A     = (const float*)d_in[1];
    const float* Win   = (const float*)d_in[2];
    const float* bin   = (const float*)d_in[3];
    const float* theta = (const float*)d_in[4];
    const float* cbias = (const float*)d_in[5];
    const float* eday  = (const float*)d_in[6];
    const float* eweek = (const float*)d_in[7];
    const float* gam   = (const float*)d_in[8];
    const float* bet   = (const float*)d_in[9];
    const int*   mi    = (const int*)d_in[10];
    const int*   wi    = (const int*)d_in[11];
    float* out = (float*)d_out;

    cudaFuncSetAttribute(k_fused,   cudaFuncAttributeMaxDynamicSharedMemorySize, 99328);
    cudaFuncSetAttribute(k_combine, cudaFuncAttributeMaxDynamicSharedMemorySize, 93952);

    k_dis_init<<<1025,256>>>(A);
    k_prepA<<<1024,256>>>(A);
    k_an2<<<dim3(8,16),256>>>();
    k_temp<<<Tdim,64>>>(eday, eweek, mi, wi);
    k_xp<<<NROWS/8,256>>>(X, Win, bin, gam, bet, out);
    k_fused<<<dim3(8,288),512,99328>>>();
    for(int it=1; it<=21; ++it)
        k_matvec<<<128,256>>>(A, it);
    k_theta<<<16,256>>>(theta);
    k_combine<<<NROWS/128,256,93952>>>(cbias, gam, bet, out + NELEM);
}